// round 11
// baseline (speedup 1.0000x reference)
#include <cuda_runtime.h>
#include <cstdint>

#define CDIM    64
#define KCODES  1024
#define HWDIM   1024
#define BM      128
#define BN      64                  // codes per chunk
#define NCHUNK  (KCODES / BN)
#define NBLOCKS (65536 / BM)

#define STX     132                 // s_x row stride (floats)

// dynamic smem layout (float offsets)
#define SF_X    0                                   // 64*132 = 8448
#define SF_B    8448                                // 2 parity x (hi 4096 + lo 4096)
#define SF_HN   (SF_B + 16384)                      // 1024
#define SF_C1   (SF_HN + KCODES)                    // 128 ints
#define SF_C2   (SF_C1 + 128)
#define SF_RS   (SF_C2 + 128)                       // 256 floats
#define SF_FIN  (SF_RS + 256)                       // 128 ints
#define SF_TOT  (SF_FIN + 128)
#define SMEM_BYTES (SF_TOT * 4)                     // 106368 B

__device__ float d_hn[KCODES];                      // 0.5*||c_k||^2
__device__ float d_cbh[KCODES * CDIM];              // tf32-hi, chunk/perm/swizzle layout
__device__ float d_cbl[KCODES * CDIM];              // tf32-lo residual

// round-to-nearest fp32 -> tf32
static __forceinline__ __device__ uint32_t f2tf(float f) {
    uint32_t r;
    asm("cvt.rna.tf32.f32 %0, %1;" : "=r"(r) : "f"(f));
    return r;
}
// m16n8k8 tf32 MMA (baseline PTX, sm_80+)
static __forceinline__ __device__ void mma8(float* c, uint32_t a0, uint32_t a1,
                                            uint32_t a2, uint32_t a3,
                                            uint32_t b0, uint32_t b1) {
    asm("mma.sync.aligned.m16n8k8.row.col.f32.tf32.tf32.f32 "
        "{%0,%1,%2,%3}, {%4,%5,%6,%7}, {%8,%9}, {%0,%1,%2,%3};"
        : "+f"(c[0]), "+f"(c[1]), "+f"(c[2]), "+f"(c[3])
        : "r"(a0), "r"(a1), "r"(a2), "r"(a3), "r"(b0), "r"(b1));
}
static __forceinline__ __device__ bool lt(float v1, int i1, float v2, int i2) {
    return v1 < v2 || (v1 == v2 && i1 < i2);
}

// ---- prep: half-norms + split codebook in fragment-native swizzled layout ----
// layout per chunk ch: [k-row 0..63][p 0..63]; code n at p = (n&7)*8 + ((n>>3) ^ ((n&4)?4:0))
__global__ void prep_kernel(const float* __restrict__ cb) {
    __shared__ float sc[64][65];                    // [code][k]
    const int ch = blockIdx.x;
    const int t  = threadIdx.x;
    #pragma unroll
    for (int i = 0; i < 4; ++i) {
        int e    = t + i * 256;                     // 1024 f4
        int code = e >> 4;
        int kf4  = e & 15;
        float4 v = __ldg(reinterpret_cast<const float4*>(cb + (ch * 64 + code) * CDIM + kf4 * 4));
        sc[code][kf4 * 4 + 0] = v.x;
        sc[code][kf4 * 4 + 1] = v.y;
        sc[code][kf4 * 4 + 2] = v.z;
        sc[code][kf4 * 4 + 3] = v.w;
    }
    __syncthreads();
    if (t < 64) {
        float s = 0.f;
        #pragma unroll
        for (int k = 0; k < 64; ++k) s += sc[t][k] * sc[t][k];
        d_hn[ch * 64 + t] = 0.5f * s;
    }
    // write split arrays; thread owns 16 consecutive physical floats (coalesced)
    const int k  = t >> 2;
    const int p0 = (t & 3) * 16;
    float hbuf[16], lbuf[16];
    #pragma unroll
    for (int j = 0; j < 16; ++j) {
        int p  = p0 + j;
        int g  = p >> 3;
        int nt = (p & 7) ^ ((g >> 2) << 2);         // undo swizzle
        int n  = nt * 8 + g;
        float f = sc[n][k];
        uint32_t h = f2tf(f);
        hbuf[j] = __uint_as_float(h);
        lbuf[j] = __uint_as_float(f2tf(f - __uint_as_float(h)));
    }
    float* dh = d_cbh + ch * 4096 + k * 64 + p0;
    float* dl = d_cbl + ch * 4096 + k * 64 + p0;
    #pragma unroll
    for (int j = 0; j < 4; ++j) {
        *reinterpret_cast<float4*>(dh + j * 4) = *reinterpret_cast<float4*>(hbuf + j * 4);
        *reinterpret_cast<float4*>(dl + j * 4) = *reinterpret_cast<float4*>(lbuf + j * 4);
    }
}

__global__ __launch_bounds__(256, 2) void vq_kernel(const float* __restrict__ x,
                                                    const float* __restrict__ cb,
                                                    float* __restrict__ out) {
    extern __shared__ float sm[];
    float* s_x  = sm + SF_X;
    float* s_hn = sm + SF_HN;
    int*   s_c1 = reinterpret_cast<int*>(sm + SF_C1);
    int*   s_c2 = reinterpret_cast<int*>(sm + SF_C2);
    float* s_rs = sm + SF_RS;
    int*   s_fin = reinterpret_cast<int*>(sm + SF_FIN);

    const int tid  = threadIdx.x;
    const int wid  = tid >> 5;
    const int lane = tid & 31;
    const int g    = lane >> 2;
    const int tig  = lane & 3;
    const int wrow = wid * 16;
    const int nbase = blockIdx.x * BM;
    const int b = nbase >> 10;
    const int p = nbase & 1023;
    const float* xin = x + b * (CDIM * HWDIM) + p;

    // ---- fill x tile ----
    #pragma unroll
    for (int i = 0; i < 8; ++i) {
        int e  = tid + i * 256;
        int kk = e >> 5;
        int r4 = e & 31;
        float4 v = *reinterpret_cast<const float4*>(xin + kk * HWDIM + r4 * 4);
        *reinterpret_cast<float4*>(s_x + kk * STX + r4 * 4) = v;
    }
    #pragma unroll
    for (int i = 0; i < 4; ++i) {
        int k = tid + i * 256;
        s_hn[k] = d_hn[k];
    }

    // ---- prefill B chunk 0 into parity buffer 0 (pure f4 copies) ----
    {
        float* dst = sm + SF_B;                     // parity 0
        #pragma unroll
        for (int i = 0; i < 4; ++i) {
            int f4 = tid + i * 256;
            *reinterpret_cast<float4*>(dst + f4 * 4) =
                *reinterpret_cast<const float4*>(d_cbh + f4 * 4);
            *reinterpret_cast<float4*>(dst + 4096 + f4 * 4) =
                *reinterpret_cast<const float4*>(d_cbl + f4 * 4);
        }
    }
    __syncthreads();

    // top-2 running state (rows wrow+g, wrow+g+8)
    float bv0 = 3.4e38f, sv0 = 3.4e38f, bv1 = 3.4e38f, sv1 = 3.4e38f;
    int   bi0 = 0, si0 = 0, bi1 = 0, si1 = 0;

    #pragma unroll 1
    for (int ch = 0; ch < NCHUNK; ++ch) {
        const int par = ch & 1;
        // fill NEXT chunk into the other parity buffer (its readers finished 2 iters ago)
        if (ch < NCHUNK - 1) {
            float* dst = sm + SF_B + (par ^ 1) * 8192;
            const float* srch = d_cbh + (ch + 1) * 4096;
            const float* srcl = d_cbl + (ch + 1) * 4096;
            #pragma unroll
            for (int i = 0; i < 4; ++i) {
                int f4 = tid + i * 256;
                *reinterpret_cast<float4*>(dst + f4 * 4) =
                    *reinterpret_cast<const float4*>(srch + f4 * 4);
                *reinterpret_cast<float4*>(dst + 4096 + f4 * 4) =
                    *reinterpret_cast<const float4*>(srcl + f4 * 4);
            }
        }

        const float* bb = sm + SF_B + par * 8192;
        float c[8][4];
        #pragma unroll
        for (int s = 0; s < 8; ++s)
            #pragma unroll
            for (int j = 0; j < 4; ++j) c[s][j] = 0.f;

        #pragma unroll
        for (int ks = 0; ks < 8; ++ks) {
            // A fragment (same mapping as R10)
            const float* ax = s_x + (ks * 8 + tig) * STX + wrow + g;
            float af0 = ax[0];
            float af1 = ax[8];
            float af2 = ax[4 * STX];
            float af3 = ax[4 * STX + 8];
            uint32_t ah0 = f2tf(af0), ah1 = f2tf(af1), ah2 = f2tf(af2), ah3 = f2tf(af3);
            uint32_t al0 = f2tf(af0 - __uint_as_float(ah0));
            uint32_t al1 = f2tf(af1 - __uint_as_float(ah1));
            uint32_t al2 = f2tf(af2 - __uint_as_float(ah2));
            uint32_t al3 = f2tf(af3 - __uint_as_float(ah3));

            // B: fragment-native rows of 64 floats; thread's 8 values contiguous
            const float* bh0p = bb + (ks * 8 + tig) * 64 + g * 8;
            const float* bh4p = bh0p + 4 * 64;
            const float* bl0p = bh0p + 4096;
            const float* bl4p = bl0p + 4 * 64;

            #pragma unroll
            for (int half = 0; half < 2; ++half) {
                float4 h0 = *reinterpret_cast<const float4*>(bh0p + half * 4);
                float4 h4 = *reinterpret_cast<const float4*>(bh4p + half * 4);
                float4 l0 = *reinterpret_cast<const float4*>(bl0p + half * 4);
                float4 l4 = *reinterpret_cast<const float4*>(bl4p + half * 4);
                #define DO_SLOT(S, BH0, BH1, BL0, BL1)                                       \
                    mma8(c[S], ah0, ah1, ah2, ah3, __float_as_uint(BH0), __float_as_uint(BH1)); \
                    mma8(c[S], ah0, ah1, ah2, ah3, __float_as_uint(BL0), __float_as_uint(BL1)); \
                    mma8(c[S], al0, al1, al2, al3, __float_as_uint(BH0), __float_as_uint(BH1));
                if (half == 0) {
                    DO_SLOT(0, h0.x, h4.x, l0.x, l4.x)
                    DO_SLOT(1, h0.y, h4.y, l0.y, l4.y)
                    DO_SLOT(2, h0.z, h4.z, l0.z, l4.z)
                    DO_SLOT(3, h0.w, h4.w, l0.w, l4.w)
                } else {
                    DO_SLOT(4, h0.x, h4.x, l0.x, l4.x)
                    DO_SLOT(5, h0.y, h4.y, l0.y, l4.y)
                    DO_SLOT(6, h0.z, h4.z, l0.z, l4.z)
                    DO_SLOT(7, h0.w, h4.w, l0.w, l4.w)
                }
                #undef DO_SLOT
            }
        }

        // ---- running top-2; swizzle-compensated column ids ----
        #pragma unroll
        for (int s = 0; s < 8; ++s) {
            int ntc  = (tig >= 2) ? (s ^ 4) : s;
            int col0 = ch * BN + ntc * 8 + 2 * tig;
            float hn0 = s_hn[col0];
            float hn1 = s_hn[col0 + 1];
            float s00 = hn0 - c[s][0];
            float s01 = hn1 - c[s][1];
            float s10 = hn0 - c[s][2];
            float s11 = hn1 - c[s][3];
            if (s00 < bv0) { sv0 = bv0; si0 = bi0; bv0 = s00; bi0 = col0; }
            else if (s00 < sv0) { sv0 = s00; si0 = col0; }
            if (s01 < bv0) { sv0 = bv0; si0 = bi0; bv0 = s01; bi0 = col0 + 1; }
            else if (s01 < sv0) { sv0 = s01; si0 = col0 + 1; }
            if (s10 < bv1) { sv1 = bv1; si1 = bi1; bv1 = s10; bi1 = col0; }
            else if (s10 < sv1) { sv1 = s10; si1 = col0; }
            if (s11 < bv1) { sv1 = bv1; si1 = bi1; bv1 = s11; bi1 = col0 + 1; }
            else if (s11 < sv1) { sv1 = s11; si1 = col0 + 1; }
        }
        __syncthreads();                            // fill(ch+1) visible; compute(ch) done
    }

    // ---- merge top-2 across the 4 lanes of each group ----
    #pragma unroll
    for (int off = 2; off > 0; off >>= 1) {
        float oB0 = __shfl_down_sync(0xffffffffu, bv0, off, 4);
        int   oBi0 = __shfl_down_sync(0xffffffffu, bi0, off, 4);
        float oS0 = __shfl_down_sync(0xffffffffu, sv0, off, 4);
        int   oSi0 = __shfl_down_sync(0xffffffffu, si0, off, 4);
        float oB1 = __shfl_down_sync(0xffffffffu, bv1, off, 4);
        int   oBi1 = __shfl_down_sync(0xffffffffu, bi1, off, 4);
        float oS1 = __shfl_down_sync(0xffffffffu, sv1, off, 4);
        int   oSi1 = __shfl_down_sync(0xffffffffu, si1, off, 4);
        if (lt(oB0, oBi0, bv0, bi0)) {
            if (lt(bv0, bi0, oS0, oSi0)) { sv0 = bv0; si0 = bi0; }
            else                         { sv0 = oS0; si0 = oSi0; }
            bv0 = oB0; bi0 = oBi0;
        } else if (lt(oB0, oBi0, sv0, si0)) { sv0 = oB0; si0 = oBi0; }
        if (lt(oB1, oBi1, bv1, bi1)) {
            if (lt(bv1, bi1, oS1, oSi1)) { sv1 = bv1; si1 = bi1; }
            else                         { sv1 = oS1; si1 = oSi1; }
            bv1 = oB1; bi1 = oBi1;
        } else if (lt(oB1, oBi1, sv1, si1)) { sv1 = oB1; si1 = oBi1; }
    }
    if (tig == 0) {
        s_c1[wrow + g]     = bi0;  s_c2[wrow + g]     = si0;
        s_c1[wrow + g + 8] = bi1;  s_c2[wrow + g + 8] = si1;
    }
    __syncthreads();

    // ---- exact fp32 refinement of the two candidates per row ----
    {
        int row  = tid >> 1;
        int cand = tid & 1;
        int idx  = cand ? s_c2[row] : s_c1[row];
        const float4* cr = reinterpret_cast<const float4*>(cb + idx * CDIM);
        float dot = 0.f;
        #pragma unroll
        for (int i = 0; i < 16; ++i) {
            float4 v = __ldg(&cr[i]);
            const float* xr = s_x + (i * 4) * STX + row;
            dot = fmaf(xr[0 * STX], v.x, dot);
            dot = fmaf(xr[1 * STX], v.y, dot);
            dot = fmaf(xr[2 * STX], v.z, dot);
            dot = fmaf(xr[3 * STX], v.w, dot);
        }
        s_rs[row * 2 + cand] = s_hn[idx] - dot;
    }
    __syncthreads();
    if (tid < 128) {
        int   i1 = s_c1[tid], i2 = s_c2[tid];
        float v1 = s_rs[tid * 2], v2 = s_rs[tid * 2 + 1];
        s_fin[tid] = lt(v2, i2, v1, i1) ? i2 : i1;
    }
    __syncthreads();

    // ---- epilogue: gather winning code vectors, NCHW coalesced float4 ----
    float* outp = out + b * (CDIM * HWDIM) + p;
    #pragma unroll
    for (int i = 0; i < 8; ++i) {
        int e   = tid + i * 256;
        int chn = e >> 5;
        int r4  = e & 31;
        int i0 = s_fin[r4 * 4 + 0];
        int i1 = s_fin[r4 * 4 + 1];
        int i2 = s_fin[r4 * 4 + 2];
        int i3 = s_fin[r4 * 4 + 3];
        float4 o;
        o.x = __ldg(&cb[i0 * CDIM + chn]);
        o.y = __ldg(&cb[i1 * CDIM + chn]);
        o.z = __ldg(&cb[i2 * CDIM + chn]);
        o.w = __ldg(&cb[i3 * CDIM + chn]);
        *reinterpret_cast<float4*>(outp + chn * HWDIM + r4 * 4) = o;
    }
}

extern "C" void kernel_launch(void* const* d_in, const int* in_sizes, int n_in,
                              void* d_out, int out_size) {
    const float* x  = (const float*)d_in[0];   // inputs  [64,64,32,32]
    const float* cb = (const float*)d_in[1];   // codebook [1024,64]
    float* out = (float*)d_out;
    cudaFuncSetAttribute(vq_kernel, cudaFuncAttributeMaxDynamicSharedMemorySize, SMEM_BYTES);
    prep_kernel<<<NCHUNK, 256>>>(cb);
    vq_kernel<<<NBLOCKS, 256, SMEM_BYTES>>>(x, cb, out);
}

// round 12
// speedup vs baseline: 1.7027x; 1.7027x over previous
#include <cuda_runtime.h>
#include <cstdint>

#define CDIM    64
#define KCODES  1024
#define HWDIM   1024
#define BM      128
#define BN      64                  // codes per chunk
#define NCHUNK  (KCODES / BN)
#define NBLOCKS (65536 / BM)
#define STX     132                 // s_x row stride (floats)

// dynamic smem layout (float offsets)
#define SF_X    0                                   // 64*132 = 8448
#define SF_B    8448                                // 8192: hi[4096] then lo[4096]
#define SF_HN   (SF_B + 8192)                       // 1024
#define SF_C1   (SF_HN + KCODES)                    // 128 ints
#define SF_C2   (SF_C1 + 128)
#define SF_RS   (SF_C2 + 128)                       // 256 floats
#define SF_FIN  (SF_RS + 256)                       // 128 ints
#define SF_TOT  (SF_FIN + 128)
#define SMEM_BYTES (SF_TOT * 4)                     // ~73 KB

__device__ float d_hn[KCODES];                      // 0.5*||c_k||^2
// per chunk: 8192 floats = [ks 0..7][row 0..3][128] hi, then same 4096 for lo.
// row r (= kb*1 + hb*2 encoding: rr&1 -> k+4, rr>>1 -> slots 4..7):
//   value at [l*4 + m] = C[code=((rr>>1)*4+m)*8 + (l>>2)][k = ks*8 + (l&3) + (rr&1)*4]
__device__ float d_cb2[NCHUNK][8192];

// round-to-nearest fp32 -> tf32
static __forceinline__ __device__ uint32_t f2tf(float f) {
    uint32_t r;
    asm("cvt.rna.tf32.f32 %0, %1;" : "=r"(r) : "f"(f));
    return r;
}
// m16n8k8 tf32 MMA (baseline PTX, sm_80+)
static __forceinline__ __device__ void mma8(float* c, uint32_t a0, uint32_t a1,
                                            uint32_t a2, uint32_t a3,
                                            uint32_t b0, uint32_t b1) {
    asm("mma.sync.aligned.m16n8k8.row.col.f32.tf32.tf32.f32 "
        "{%0,%1,%2,%3}, {%4,%5,%6,%7}, {%8,%9}, {%0,%1,%2,%3};"
        : "+f"(c[0]), "+f"(c[1]), "+f"(c[2]), "+f"(c[3])
        : "r"(a0), "r"(a1), "r"(a2), "r"(a3), "r"(b0), "r"(b1));
}
static __forceinline__ __device__ bool lt(float v1, int i1, float v2, int i2) {
    return v1 < v2 || (v1 == v2 && i1 < i2);
}

// ---- prep: half-norms + split codebook in lane-contiguous fragment layout ----
__global__ void prep_kernel(const float* __restrict__ cb) {
    __shared__ float sc[64][65];                    // [code][k]
    const int ch = blockIdx.x;
    const int t  = threadIdx.x;
    #pragma unroll
    for (int i = 0; i < 4; ++i) {
        int e    = t + i * 256;                     // 1024 f4
        int code = e >> 4;
        int kf4  = e & 15;
        float4 v = __ldg(reinterpret_cast<const float4*>(cb + (ch * 64 + code) * CDIM + kf4 * 4));
        sc[code][kf4 * 4 + 0] = v.x;
        sc[code][kf4 * 4 + 1] = v.y;
        sc[code][kf4 * 4 + 2] = v.z;
        sc[code][kf4 * 4 + 3] = v.w;
    }
    __syncthreads();
    if (t < 64) {
        float s = 0.f;
        #pragma unroll
        for (int k = 0; k < 64; ++k) s += sc[t][k] * sc[t][k];
        d_hn[ch * 64 + t] = 0.5f * s;
    }
    #pragma unroll
    for (int i = 0; i < 16; ++i) {
        int o   = t + i * 256;                      // 0..4095, coalesced
        int ks  = o >> 9;
        int rr  = (o >> 7) & 3;
        int l   = (o >> 2) & 31;
        int m   = o & 3;
        int g   = l >> 2;
        int tig = l & 3;
        int code = ((rr >> 1) * 4 + m) * 8 + g;
        int k    = ks * 8 + tig + (rr & 1) * 4;
        float f = sc[code][k];
        uint32_t h = f2tf(f);
        d_cb2[ch][o]        = __uint_as_float(h);
        d_cb2[ch][4096 + o] = __uint_as_float(f2tf(f - __uint_as_float(h)));
    }
}

__global__ __launch_bounds__(256, 2) void vq_kernel(const float* __restrict__ x,
                                                    const float* __restrict__ cb,
                                                    float* __restrict__ out) {
    extern __shared__ float sm[];
    float* s_x  = sm + SF_X;
    float* s_b  = sm + SF_B;
    float* s_hn = sm + SF_HN;
    int*   s_c1 = reinterpret_cast<int*>(sm + SF_C1);
    int*   s_c2 = reinterpret_cast<int*>(sm + SF_C2);
    float* s_rs = sm + SF_RS;
    int*   s_fin = reinterpret_cast<int*>(sm + SF_FIN);

    const int tid  = threadIdx.x;
    const int wid  = tid >> 5;
    const int lane = tid & 31;
    const int g    = lane >> 2;
    const int tig  = lane & 3;
    const int wrow = wid * 16;
    const int nbase = blockIdx.x * BM;
    const int b = nbase >> 10;
    const int p = nbase & 1023;
    const float* xin = x + b * (CDIM * HWDIM) + p;

    // ---- fill x tile (kk-major, stride 132) ----
    #pragma unroll
    for (int i = 0; i < 8; ++i) {
        int e  = tid + i * 256;
        int kk = e >> 5;
        int r4 = e & 31;
        float4 v = *reinterpret_cast<const float4*>(xin + kk * HWDIM + r4 * 4);
        *reinterpret_cast<float4*>(s_x + kk * STX + r4 * 4) = v;
    }
    #pragma unroll
    for (int i = 0; i < 4; ++i) {
        int k = tid + i * 256;
        s_hn[k] = d_hn[k];
    }

    // top-2 running state (rows wrow+g, wrow+g+8)
    float bv0 = 3.4e38f, sv0 = 3.4e38f, bv1 = 3.4e38f, sv1 = 3.4e38f;
    int   bi0 = 0, si0 = 0, bi1 = 0, si1 = 0;

    #pragma unroll 1
    for (int ch = 0; ch < NCHUNK; ++ch) {
        // ---- fill B chunk: pure f4 copy, coalesced ----
        #pragma unroll
        for (int i = 0; i < 8; ++i) {
            int f4 = tid + i * 256;                 // 2048 f4 = 8192 floats
            reinterpret_cast<float4*>(s_b)[f4] =
                *reinterpret_cast<const float4*>(&d_cb2[ch][f4 * 4]);
        }
        __syncthreads();

        float c[8][4];
        #pragma unroll
        for (int s = 0; s < 8; ++s)
            #pragma unroll
            for (int j = 0; j < 4; ++j) c[s][j] = 0.f;

        #pragma unroll
        for (int ks = 0; ks < 8; ++ks) {
            // A fragment: identical to verified R10 path
            const float* ax = s_x + (ks * 8 + tig) * STX + wrow + g;
            float af0 = ax[0];
            float af1 = ax[8];
            float af2 = ax[4 * STX];
            float af3 = ax[4 * STX + 8];
            uint32_t ah0 = f2tf(af0), ah1 = f2tf(af1), ah2 = f2tf(af2), ah3 = f2tf(af3);
            uint32_t al0 = f2tf(af0 - __uint_as_float(ah0));
            uint32_t al1 = f2tf(af1 - __uint_as_float(ah1));
            uint32_t al2 = f2tf(af2 - __uint_as_float(ah2));
            uint32_t al3 = f2tf(af3 - __uint_as_float(ah3));

            // B: four 512-B rows (hi) + four (lo); lane l at byte l*16 — conflict-free
            const float* bp = s_b + ks * 512 + lane * 4;
            float4 hA = *reinterpret_cast<const float4*>(bp);          // b0, slots 0-3
            float4 hB = *reinterpret_cast<const float4*>(bp + 128);    // b1, slots 0-3
            float4 hC = *reinterpret_cast<const float4*>(bp + 256);    // b0, slots 4-7
            float4 hD = *reinterpret_cast<const float4*>(bp + 384);    // b1, slots 4-7
            float4 lA = *reinterpret_cast<const float4*>(bp + 4096);
            float4 lB = *reinterpret_cast<const float4*>(bp + 4224);
            float4 lC = *reinterpret_cast<const float4*>(bp + 4352);
            float4 lD = *reinterpret_cast<const float4*>(bp + 4480);

            #define FU(v) __float_as_uint(v)
            #define SLOT(S, H0, H1, L0, L1)                        \
                mma8(c[S], ah0, ah1, ah2, ah3, FU(H0), FU(H1));    \
                mma8(c[S], ah0, ah1, ah2, ah3, FU(L0), FU(L1));    \
                mma8(c[S], al0, al1, al2, al3, FU(H0), FU(H1));
            SLOT(0, hA.x, hB.x, lA.x, lB.x)
            SLOT(1, hA.y, hB.y, lA.y, lB.y)
            SLOT(2, hA.z, hB.z, lA.z, lB.z)
            SLOT(3, hA.w, hB.w, lA.w, lB.w)
            SLOT(4, hC.x, hD.x, lC.x, lD.x)
            SLOT(5, hC.y, hD.y, lC.y, lD.y)
            SLOT(6, hC.z, hD.z, lC.z, lD.z)
            SLOT(7, hC.w, hD.w, lC.w, lD.w)
            #undef SLOT
            #undef FU
        }

        // ---- running top-2 (ascending col order; same mapping as R10) ----
        #pragma unroll
        for (int s = 0; s < 8; ++s) {
            int col0 = ch * BN + s * 8 + 2 * tig;
            float hn0 = s_hn[col0];
            float hn1 = s_hn[col0 + 1];
            float s00 = hn0 - c[s][0];
            float s01 = hn1 - c[s][1];
            float s10 = hn0 - c[s][2];
            float s11 = hn1 - c[s][3];
            if (s00 < bv0) { sv0 = bv0; si0 = bi0; bv0 = s00; bi0 = col0; }
            else if (s00 < sv0) { sv0 = s00; si0 = col0; }
            if (s01 < bv0) { sv0 = bv0; si0 = bi0; bv0 = s01; bi0 = col0 + 1; }
            else if (s01 < sv0) { sv0 = s01; si0 = col0 + 1; }
            if (s10 < bv1) { sv1 = bv1; si1 = bi1; bv1 = s10; bi1 = col0; }
            else if (s10 < sv1) { sv1 = s10; si1 = col0; }
            if (s11 < bv1) { sv1 = bv1; si1 = bi1; bv1 = s11; bi1 = col0 + 1; }
            else if (s11 < sv1) { sv1 = s11; si1 = col0 + 1; }
        }
        __syncthreads();                            // readers done before next fill
    }

    // ---- merge top-2 across the 4 lanes of each group ----
    #pragma unroll
    for (int off = 2; off > 0; off >>= 1) {
        float oB0 = __shfl_down_sync(0xffffffffu, bv0, off, 4);
        int   oBi0 = __shfl_down_sync(0xffffffffu, bi0, off, 4);
        float oS0 = __shfl_down_sync(0xffffffffu, sv0, off, 4);
        int   oSi0 = __shfl_down_sync(0xffffffffu, si0, off, 4);
        float oB1 = __shfl_down_sync(0xffffffffu, bv1, off, 4);
        int   oBi1 = __shfl_down_sync(0xffffffffu, bi1, off, 4);
        float oS1 = __shfl_down_sync(0xffffffffu, sv1, off, 4);
        int   oSi1 = __shfl_down_sync(0xffffffffu, si1, off, 4);
        if (lt(oB0, oBi0, bv0, bi0)) {
            if (lt(bv0, bi0, oS0, oSi0)) { sv0 = bv0; si0 = bi0; }
            else                         { sv0 = oS0; si0 = oSi0; }
            bv0 = oB0; bi0 = oBi0;
        } else if (lt(oB0, oBi0, sv0, si0)) { sv0 = oB0; si0 = oBi0; }
        if (lt(oB1, oBi1, bv1, bi1)) {
            if (lt(bv1, bi1, oS1, oSi1)) { sv1 = bv1; si1 = bi1; }
            else                         { sv1 = oS1; si1 = oSi1; }
            bv1 = oB1; bi1 = oBi1;
        } else if (lt(oB1, oBi1, sv1, si1)) { sv1 = oB1; si1 = oBi1; }
    }
    if (tig == 0) {
        s_c1[wrow + g]     = bi0;  s_c2[wrow + g]     = si0;
        s_c1[wrow + g + 8] = bi1;  s_c2[wrow + g + 8] = si1;
    }
    __syncthreads();

    // ---- exact fp32 refinement of the two candidates per row ----
    {
        int row  = tid >> 1;
        int cand = tid & 1;
        int idx  = cand ? s_c2[row] : s_c1[row];
        const float4* cr = reinterpret_cast<const float4*>(cb + idx * CDIM);
        float dot = 0.f;
        #pragma unroll
        for (int i = 0; i < 16; ++i) {
            float4 v = __ldg(&cr[i]);
            const float* xr = s_x + (i * 4) * STX + row;
            dot = fmaf(xr[0 * STX], v.x, dot);
            dot = fmaf(xr[1 * STX], v.y, dot);
            dot = fmaf(xr[2 * STX], v.z, dot);
            dot = fmaf(xr[3 * STX], v.w, dot);
        }
        s_rs[row * 2 + cand] = s_hn[idx] - dot;
    }
    __syncthreads();
    if (tid < 128) {
        int   i1 = s_c1[tid], i2 = s_c2[tid];
        float v1 = s_rs[tid * 2], v2 = s_rs[tid * 2 + 1];
        s_fin[tid] = lt(v2, i2, v1, i1) ? i2 : i1;
    }
    __syncthreads();

    // ---- epilogue: gather winning code vectors, NCHW coalesced float4 ----
    float* outp = out + b * (CDIM * HWDIM) + p;
    #pragma unroll
    for (int i = 0; i < 8; ++i) {
        int e   = tid + i * 256;
        int chn = e >> 5;
        int r4  = e & 31;
        int i0 = s_fin[r4 * 4 + 0];
        int i1 = s_fin[r4 * 4 + 1];
        int i2 = s_fin[r4 * 4 + 2];
        int i3 = s_fin[r4 * 4 + 3];
        float4 o;
        o.x = __ldg(&cb[i0 * CDIM + chn]);
        o.y = __ldg(&cb[i1 * CDIM + chn]);
        o.z = __ldg(&cb[i2 * CDIM + chn]);
        o.w = __ldg(&cb[i3 * CDIM + chn]);
        *reinterpret_cast<float4*>(outp + chn * HWDIM + r4 * 4) = o;
    }
}

extern "C" void kernel_launch(void* const* d_in, const int* in_sizes, int n_in,
                              void* d_out, int out_size) {
    const float* x  = (const float*)d_in[0];   // inputs  [64,64,32,32]
    const float* cb = (const float*)d_in[1];   // codebook [1024,64]
    float* out = (float*)d_out;
    cudaFuncSetAttribute(vq_kernel, cudaFuncAttributeMaxDynamicSharedMemorySize, SMEM_BYTES);
    prep_kernel<<<NCHUNK, 256>>>(cb);
    vq_kernel<<<NBLOCKS, 256, SMEM_BYTES>>>(x, cb, out);
}

// round 13
// speedup vs baseline: 1.8825x; 1.1056x over previous
#include <cuda_runtime.h>
#include <cstdint>

#define CDIM    64
#define KCODES  1024
#define HWDIM   1024
#define BM      128
#define BN      64                  // codes per chunk
#define NCHUNK  (KCODES / BN)
#define NBLOCKS (65536 / BM)

// dynamic smem layout (float offsets)
#define SF_AH   0                                   // 8192: [ks][wid][lane*4] hi
#define SF_AL   8192                                // 8192: lo
#define SF_HN   16384                               // 1024
#define SF_C1   (SF_HN + KCODES)                    // 128 ints
#define SF_C2   (SF_C1 + 128)
#define SF_RS   (SF_C2 + 128)                       // 256 floats
#define SF_FIN  (SF_RS + 256)                       // 128 ints
#define SF_TOT  (SF_FIN + 128)
#define SMEM_BYTES (SF_TOT * 4)                     // 72192 B

__device__ float d_hn[KCODES];                      // 0.5*||c_k||^2
// per chunk: 8192 floats = [ks][row 0..3][128] hi, then 4096 lo (see prep)
__device__ float d_cb2[NCHUNK][8192];

// round-to-nearest fp32 -> tf32
static __forceinline__ __device__ uint32_t f2tf(float f) {
    uint32_t r;
    asm("cvt.rna.tf32.f32 %0, %1;" : "=r"(r) : "f"(f));
    return r;
}
// m16n8k8 tf32 MMA (baseline PTX, sm_80+)
static __forceinline__ __device__ void mma8(float* c, uint32_t a0, uint32_t a1,
                                            uint32_t a2, uint32_t a3,
                                            uint32_t b0, uint32_t b1) {
    asm("mma.sync.aligned.m16n8k8.row.col.f32.tf32.tf32.f32 "
        "{%0,%1,%2,%3}, {%4,%5,%6,%7}, {%8,%9}, {%0,%1,%2,%3};"
        : "+f"(c[0]), "+f"(c[1]), "+f"(c[2]), "+f"(c[3])
        : "r"(a0), "r"(a1), "r"(a2), "r"(a3), "r"(b0), "r"(b1));
}
static __forceinline__ __device__ bool lt(float v1, int i1, float v2, int i2) {
    return v1 < v2 || (v1 == v2 && i1 < i2);
}

// ---- prep: half-norms + split codebook in lane-contiguous fragment layout ----
__global__ void prep_kernel(const float* __restrict__ cb) {
    __shared__ float sc[64][65];                    // [code][k]
    const int ch = blockIdx.x;
    const int t  = threadIdx.x;
    #pragma unroll
    for (int i = 0; i < 4; ++i) {
        int e    = t + i * 256;                     // 1024 f4
        int code = e >> 4;
        int kf4  = e & 15;
        float4 v = __ldg(reinterpret_cast<const float4*>(cb + (ch * 64 + code) * CDIM + kf4 * 4));
        sc[code][kf4 * 4 + 0] = v.x;
        sc[code][kf4 * 4 + 1] = v.y;
        sc[code][kf4 * 4 + 2] = v.z;
        sc[code][kf4 * 4 + 3] = v.w;
    }
    __syncthreads();
    if (t < 64) {
        float s = 0.f;
        #pragma unroll
        for (int k = 0; k < 64; ++k) s += sc[t][k] * sc[t][k];
        d_hn[ch * 64 + t] = 0.5f * s;
    }
    #pragma unroll
    for (int i = 0; i < 16; ++i) {
        int o   = t + i * 256;                      // 0..4095, coalesced
        int ks  = o >> 9;
        int rr  = (o >> 7) & 3;
        int l   = (o >> 2) & 31;
        int m   = o & 3;
        int g   = l >> 2;
        int tig = l & 3;
        int code = ((rr >> 1) * 4 + m) * 8 + g;
        int k    = ks * 8 + tig + (rr & 1) * 4;
        float f = sc[code][k];
        uint32_t h = f2tf(f);
        d_cb2[ch][o]        = __uint_as_float(h);
        d_cb2[ch][4096 + o] = __uint_as_float(f2tf(f - __uint_as_float(h)));
    }
}

__global__ __launch_bounds__(256, 2) void vq_kernel(const float* __restrict__ x,
                                                    const float* __restrict__ cb,
                                                    float* __restrict__ out) {
    extern __shared__ float sm[];
    float* s_ah = sm + SF_AH;
    float* s_al = sm + SF_AL;
    float* s_hn = sm + SF_HN;
    int*   s_c1 = reinterpret_cast<int*>(sm + SF_C1);
    int*   s_c2 = reinterpret_cast<int*>(sm + SF_C2);
    float* s_rs = sm + SF_RS;
    int*   s_fin = reinterpret_cast<int*>(sm + SF_FIN);

    const int tid  = threadIdx.x;
    const int wid  = tid >> 5;
    const int lane = tid & 31;
    const int g    = lane >> 2;
    const int tig  = lane & 3;
    const int wrow = wid * 16;
    const int nbase = blockIdx.x * BM;
    const int b = nbase >> 10;
    const int p = nbase & 1023;
    const float* xin = x + b * (CDIM * HWDIM) + p;

    // ---- prologue: per-thread A-fragment split, once (chunk-invariant) ----
    // s_ah[ks*1024 + wid*128 + lane*4 .. +3] = (ah0, ah1, ah2, ah3); s_al likewise
    {
        const int aoff = wid * 128 + lane * 4;
        #pragma unroll
        for (int ks = 0; ks < 8; ++ks) {
            int k0 = ks * 8 + tig;
            float af0 = __ldg(xin + k0 * HWDIM + wrow + g);
            float af1 = __ldg(xin + k0 * HWDIM + wrow + g + 8);
            float af2 = __ldg(xin + (k0 + 4) * HWDIM + wrow + g);
            float af3 = __ldg(xin + (k0 + 4) * HWDIM + wrow + g + 8);
            uint32_t h0 = f2tf(af0), h1 = f2tf(af1), h2 = f2tf(af2), h3 = f2tf(af3);
            float4 hv = make_float4(__uint_as_float(h0), __uint_as_float(h1),
                                    __uint_as_float(h2), __uint_as_float(h3));
            float4 lv = make_float4(
                __uint_as_float(f2tf(af0 - __uint_as_float(h0))),
                __uint_as_float(f2tf(af1 - __uint_as_float(h1))),
                __uint_as_float(f2tf(af2 - __uint_as_float(h2))),
                __uint_as_float(f2tf(af3 - __uint_as_float(h3))));
            *reinterpret_cast<float4*>(s_ah + ks * 1024 + aoff) = hv;
            *reinterpret_cast<float4*>(s_al + ks * 1024 + aoff) = lv;
        }
    }
    #pragma unroll
    for (int i = 0; i < 4; ++i) {
        int k = tid + i * 256;
        s_hn[k] = d_hn[k];
    }
    __syncthreads();                                // hn visible to all

    // top-2 running state (rows wrow+g, wrow+g+8)
    float bv0 = 3.4e38f, sv0 = 3.4e38f, bv1 = 3.4e38f, sv1 = 3.4e38f;
    int   bi0 = 0, si0 = 0, bi1 = 0, si1 = 0;

    const int aoff = wid * 128 + lane * 4;

    #pragma unroll 1
    for (int ch = 0; ch < NCHUNK; ++ch) {
        const float* bg = &d_cb2[ch][0] + lane * 4;
        float c[8][4];
        #pragma unroll
        for (int s = 0; s < 8; ++s)
            #pragma unroll
            for (int j = 0; j < 4; ++j) c[s][j] = 0.f;

        #pragma unroll
        for (int ks = 0; ks < 8; ++ks) {
            // B fragments: global, lane-contiguous, L1/L2-hot
            const float* bp = bg + ks * 512;
            float4 hA = __ldg(reinterpret_cast<const float4*>(bp));          // b0 slots 0-3
            float4 hB = __ldg(reinterpret_cast<const float4*>(bp + 128));    // b1 slots 0-3
            float4 hC = __ldg(reinterpret_cast<const float4*>(bp + 256));    // b0 slots 4-7
            float4 hD = __ldg(reinterpret_cast<const float4*>(bp + 384));    // b1 slots 4-7
            float4 lA = __ldg(reinterpret_cast<const float4*>(bp + 4096));
            float4 lB = __ldg(reinterpret_cast<const float4*>(bp + 4224));
            float4 lC = __ldg(reinterpret_cast<const float4*>(bp + 4352));
            float4 lD = __ldg(reinterpret_cast<const float4*>(bp + 4480));
            // A fragments: two LDS.128, conflict-free
            float4 ah = *reinterpret_cast<const float4*>(s_ah + ks * 1024 + aoff);
            float4 al = *reinterpret_cast<const float4*>(s_al + ks * 1024 + aoff);
            uint32_t ah0 = __float_as_uint(ah.x), ah1 = __float_as_uint(ah.y);
            uint32_t ah2 = __float_as_uint(ah.z), ah3 = __float_as_uint(ah.w);
            uint32_t al0 = __float_as_uint(al.x), al1 = __float_as_uint(al.y);
            uint32_t al2 = __float_as_uint(al.z), al3 = __float_as_uint(al.w);

            #define FU(v) __float_as_uint(v)
            #define SLOT(S, H0, H1, L0, L1)                        \
                mma8(c[S], ah0, ah1, ah2, ah3, FU(H0), FU(H1));    \
                mma8(c[S], ah0, ah1, ah2, ah3, FU(L0), FU(L1));    \
                mma8(c[S], al0, al1, al2, al3, FU(H0), FU(H1));
            SLOT(0, hA.x, hB.x, lA.x, lB.x)
            SLOT(1, hA.y, hB.y, lA.y, lB.y)
            SLOT(2, hA.z, hB.z, lA.z, lB.z)
            SLOT(3, hA.w, hB.w, lA.w, lB.w)
            SLOT(4, hC.x, hD.x, lC.x, lD.x)
            SLOT(5, hC.y, hD.y, lC.y, lD.y)
            SLOT(6, hC.z, hD.z, lC.z, lD.z)
            SLOT(7, hC.w, hD.w, lC.w, lD.w)
            #undef SLOT
            #undef FU
        }

        // ---- running top-2 (ascending col order; verified R10/R12 mapping) ----
        #pragma unroll
        for (int s = 0; s < 8; ++s) {
            int col0 = ch * BN + s * 8 + 2 * tig;
            float hn0 = s_hn[col0];
            float hn1 = s_hn[col0 + 1];
            float s00 = hn0 - c[s][0];
            float s01 = hn1 - c[s][1];
            float s10 = hn0 - c[s][2];
            float s11 = hn1 - c[s][3];
            if (s00 < bv0) { sv0 = bv0; si0 = bi0; bv0 = s00; bi0 = col0; }
            else if (s00 < sv0) { sv0 = s00; si0 = col0; }
            if (s01 < bv0) { sv0 = bv0; si0 = bi0; bv0 = s01; bi0 = col0 + 1; }
            else if (s01 < sv0) { sv0 = s01; si0 = col0 + 1; }
            if (s10 < bv1) { sv1 = bv1; si1 = bi1; bv1 = s10; bi1 = col0; }
            else if (s10 < sv1) { sv1 = s10; si1 = col0; }
            if (s11 < bv1) { sv1 = bv1; si1 = bi1; bv1 = s11; bi1 = col0 + 1; }
            else if (s11 < sv1) { sv1 = s11; si1 = col0 + 1; }
        }
    }

    // ---- merge top-2 across the 4 lanes of each group ----
    #pragma unroll
    for (int off = 2; off > 0; off >>= 1) {
        float oB0 = __shfl_down_sync(0xffffffffu, bv0, off, 4);
        int   oBi0 = __shfl_down_sync(0xffffffffu, bi0, off, 4);
        float oS0 = __shfl_down_sync(0xffffffffu, sv0, off, 4);
        int   oSi0 = __shfl_down_sync(0xffffffffu, si0, off, 4);
        float oB1 = __shfl_down_sync(0xffffffffu, bv1, off, 4);
        int   oBi1 = __shfl_down_sync(0xffffffffu, bi1, off, 4);
        float oS1 = __shfl_down_sync(0xffffffffu, sv1, off, 4);
        int   oSi1 = __shfl_down_sync(0xffffffffu, si1, off, 4);
        if (lt(oB0, oBi0, bv0, bi0)) {
            if (lt(bv0, bi0, oS0, oSi0)) { sv0 = bv0; si0 = bi0; }
            else                         { sv0 = oS0; si0 = oSi0; }
            bv0 = oB0; bi0 = oBi0;
        } else if (lt(oB0, oBi0, sv0, si0)) { sv0 = oB0; si0 = oBi0; }
        if (lt(oB1, oBi1, bv1, bi1)) {
            if (lt(bv1, bi1, oS1, oSi1)) { sv1 = bv1; si1 = bi1; }
            else                         { sv1 = oS1; si1 = oSi1; }
            bv1 = oB1; bi1 = oBi1;
        } else if (lt(oB1, oBi1, sv1, si1)) { sv1 = oB1; si1 = oBi1; }
    }
    if (tig == 0) {
        s_c1[wrow + g]     = bi0;  s_c2[wrow + g]     = si0;
        s_c1[wrow + g + 8] = bi1;  s_c2[wrow + g + 8] = si1;
    }
    __syncthreads();

    // ---- exact fp32 refinement of the two candidates per row (x from L2) ----
    {
        int row  = tid >> 1;
        int cand = tid & 1;
        int idx  = cand ? s_c2[row] : s_c1[row];
        const float4* cr = reinterpret_cast<const float4*>(cb + idx * CDIM);
        float dot = 0.f;
        #pragma unroll
        for (int i = 0; i < 16; ++i) {
            float4 v = __ldg(&cr[i]);
            const float* xr = xin + (i * 4) * HWDIM + row;
            dot = fmaf(__ldg(xr + 0 * HWDIM), v.x, dot);
            dot = fmaf(__ldg(xr + 1 * HWDIM), v.y, dot);
            dot = fmaf(__ldg(xr + 2 * HWDIM), v.z, dot);
            dot = fmaf(__ldg(xr + 3 * HWDIM), v.w, dot);
        }
        s_rs[row * 2 + cand] = s_hn[idx] - dot;
    }
    __syncthreads();
    if (tid < 128) {
        int   i1 = s_c1[tid], i2 = s_c2[tid];
        float v1 = s_rs[tid * 2], v2 = s_rs[tid * 2 + 1];
        s_fin[tid] = lt(v2, i2, v1, i1) ? i2 : i1;
    }
    __syncthreads();

    // ---- epilogue: gather winning code vectors, NCHW coalesced float4 ----
    float* outp = out + b * (CDIM * HWDIM) + p;
    #pragma unroll
    for (int i = 0; i < 8; ++i) {
        int e   = tid + i * 256;
        int chn = e >> 5;
        int r4  = e & 31;
        int i0 = s_fin[r4 * 4 + 0];
        int i1 = s_fin[r4 * 4 + 1];
        int i2 = s_fin[r4 * 4 + 2];
        int i3 = s_fin[r4 * 4 + 3];
        float4 o;
        o.x = __ldg(&cb[i0 * CDIM + chn]);
        o.y = __ldg(&cb[i1 * CDIM + chn]);
        o.z = __ldg(&cb[i2 * CDIM + chn]);
        o.w = __ldg(&cb[i3 * CDIM + chn]);
        *reinterpret_cast<float4*>(outp + chn * HWDIM + r4 * 4) = o;
    }
}

extern "C" void kernel_launch(void* const* d_in, const int* in_sizes, int n_in,
                              void* d_out, int out_size) {
    const float* x  = (const float*)d_in[0];   // inputs  [64,64,32,32]
    const float* cb = (const float*)d_in[1];   // codebook [1024,64]
    float* out = (float*)d_out;
    cudaFuncSetAttribute(vq_kernel, cudaFuncAttributeMaxDynamicSharedMemorySize, SMEM_BYTES);
    prep_kernel<<<NCHUNK, 256>>>(cb);
    vq_kernel<<<NBLOCKS, 256, SMEM_BYTES>>>(x, cb, out);
}